// round 1
// baseline (speedup 1.0000x reference)
#include <cuda_runtime.h>

#define Bn 32
#define Hn 512
#define Wn 512
#define EPSf 1e-7f
#define DTf 0.05f

// tile config for main kernel
#define TX 32
#define TY 16
#define RX (TX + 4)   // 36 raw halo tile
#define RY (TY + 4)   // 20
#define EX (TX + 2)   // 34 extended intermediate tile
#define EY (TY + 2)   // 18

__device__ unsigned int g_max_bits;

__global__ void init_max_kernel() { g_max_bits = 0u; }

__device__ __forceinline__ float imgAt(const float* __restrict__ p, int b, int y, int x) {
    if ((unsigned)y < (unsigned)Hn && (unsigned)x < (unsigned)Wn)
        return p[((size_t)b * Hn + y) * Wn + x];
    return 0.0f;
}

// Pass 1: max over e = ((sobel_x)^2 + (sobel_y)^2)^2
__global__ void reduce_max_kernel(const float* __restrict__ img) {
    int x = blockIdx.x * blockDim.x + threadIdx.x;
    int y = blockIdx.y;
    int b = blockIdx.z;
    float e = 0.0f;
    if (x < Wn) {
        float a00 = imgAt(img, b, y - 1, x - 1);
        float a01 = imgAt(img, b, y - 1, x);
        float a02 = imgAt(img, b, y - 1, x + 1);
        float a10 = imgAt(img, b, y,     x - 1);
        float a12 = imgAt(img, b, y,     x + 1);
        float a20 = imgAt(img, b, y + 1, x - 1);
        float a21 = imgAt(img, b, y + 1, x);
        float a22 = imgAt(img, b, y + 1, x + 1);
        float ex = (a00 - a02) + 2.0f * (a10 - a12) + (a20 - a22);
        float ey = (a00 - a20) + 2.0f * (a01 - a21) + (a02 - a22);
        float s = ex * ex + ey * ey;
        e = s * s;
    }
    // warp max
    #pragma unroll
    for (int o = 16; o > 0; o >>= 1)
        e = fmaxf(e, __shfl_xor_sync(0xffffffffu, e, o));
    __shared__ float wmax[8];
    int lane = threadIdx.x & 31;
    int w = threadIdx.x >> 5;
    if (lane == 0) wmax[w] = e;
    __syncthreads();
    if (threadIdx.x < 8) {
        float m = wmax[threadIdx.x];
        #pragma unroll
        for (int o = 4; o > 0; o >>= 1)
            m = fmaxf(m, __shfl_xor_sync(0xffu, m, o));
        if (threadIdx.x == 0)
            atomicMax(&g_max_bits, __float_as_uint(m));  // valid: all e >= 0
    }
}

// Pass 2: fully fused forcing function
__global__ __launch_bounds__(TX * TY) void forcing_kernel(
    const float* __restrict__ u,
    const float* __restrict__ img,
    const float* __restrict__ alpha_p,
    const float* __restrict__ beta_p,
    const float* __restrict__ gamma_p,
    float* __restrict__ out)
{
    __shared__ float s_img[RY][RX];
    __shared__ float s_u[RY][RX];
    __shared__ float s_edges[EY][EX];
    __shared__ float s_px[EY][EX];
    __shared__ float s_py[EY][EX];

    const int tx = threadIdx.x;
    const int ty = threadIdx.y;
    const int tid = ty * TX + tx;
    const int x0 = blockIdx.x * TX;
    const int y0 = blockIdx.y * TY;
    const int b  = blockIdx.z;

    const float* imgB = img + (size_t)b * Hn * Wn;
    const float* uB   = u   + (size_t)b * Hn * Wn;

    // --- load raw halo tiles (zero-padded SAME) ---
    for (int i = tid; i < RY * RX; i += TX * TY) {
        int ry = i / RX, rx = i % RX;
        int gy = y0 - 2 + ry;
        int gx = x0 - 2 + rx;
        float iv = 0.0f, uv = 0.0f;
        if ((unsigned)gy < (unsigned)Hn && (unsigned)gx < (unsigned)Wn) {
            size_t off = (size_t)gy * Wn + gx;
            iv = imgB[off];
            uv = uB[off];
        }
        s_img[ry][rx] = iv;
        s_u[ry][rx] = uv;
    }
    __syncthreads();

    const float maxv = __uint_as_float(g_max_bits);

    // --- compute extended intermediates: edges, px, py over (EY x EX) ---
    for (int i = tid; i < EY * EX; i += TX * TY) {
        int eyi = i / EX, exi = i % EX;
        int ry = eyi + 1, rx = exi + 1;   // raw-tile coords (1..RY-2, 1..RX-2)
        int gy = y0 - 1 + eyi;
        int gx = x0 - 1 + exi;
        float edges = 0.0f, px = 0.0f, py = 0.0f;
        if ((unsigned)gy < (unsigned)Hn && (unsigned)gx < (unsigned)Wn) {
            // edges from img sobel (zero-padded img already in smem)
            float a00 = s_img[ry - 1][rx - 1];
            float a01 = s_img[ry - 1][rx];
            float a02 = s_img[ry - 1][rx + 1];
            float a10 = s_img[ry][rx - 1];
            float a12 = s_img[ry][rx + 1];
            float a20 = s_img[ry + 1][rx - 1];
            float a21 = s_img[ry + 1][rx];
            float a22 = s_img[ry + 1][rx + 1];
            float sx = (a00 - a02) + 2.0f * (a10 - a12) + (a20 - a22);
            float sy = (a00 - a20) + 2.0f * (a01 - a21) + (a02 - a22);
            float s = sx * sx + sy * sy;
            float e = s * s;
            edges = 1.0f / (e / maxv + 1.0f);
            // normalized gradient of u
            float gux = s_u[ry][rx + 1] - s_u[ry][rx - 1];
            float guy = s_u[ry - 1][rx] - s_u[ry + 1][rx];
            float normu = sqrtf(gux * gux + guy * guy + EPSf);
            float inv = 1.0f / (normu + EPSf);
            px = gux * inv;
            py = guy * inv;
        }
        s_edges[eyi][exi] = edges;
        s_px[eyi][exi] = px;
        s_py[eyi][exi] = py;
    }
    __syncthreads();

    // --- interior: one output pixel per thread ---
    // extended coords of center: (ty+1, tx+1); raw coords: (ty+2, tx+2)
    const int ey_c = ty + 1, ex_c = tx + 1;
    const int ry_c = ty + 2, rx_c = tx + 2;

    float u_c = s_u[ry_c][rx_c];
    float uxp = s_u[ry_c][rx_c + 1];
    float uxm = s_u[ry_c][rx_c - 1];
    float uyp = s_u[ry_c - 1][rx_c];   // row y-1
    float uym = s_u[ry_c + 1][rx_c];   // row y+1

    // upwind diffs
    float xp = uxp - u_c;
    float xn = u_c - uxm;
    float yp = uyp - u_c;
    float yn = u_c - uym;

    // center gradient & norm (recompute; u tile still in smem)
    float gux = uxp - uxm;
    float guy = uyp - uym;
    float normu = sqrtf(gux * gux + guy * guy + EPSf);

    // central diffs of edges
    float gex = s_edges[ey_c][ex_c + 1] - s_edges[ey_c][ex_c - 1];
    float gey = s_edges[ey_c - 1][ex_c] - s_edges[ey_c + 1][ex_c];
    float edges_c = s_edges[ey_c][ex_c];

    // curvature = div of normalized gradient
    float kappa = (s_px[ey_c][ex_c + 1] - s_px[ey_c][ex_c - 1])
                + (s_py[ey_c - 1][ex_c] - s_py[ey_c + 1][ex_c]);

    float fxp = fmaxf(gex, 0.0f);
    float fxn = fminf(gex, 0.0f);
    float fyp = fmaxf(gey, 0.0f);
    float fyn = fminf(gey, 0.0f);
    float transport = 20.0f * ((fxp * xp + fxn * xn) + (fyp * yp + fyn * yn));

    float curvature = edges_c * kappa * normu;
    float balloon   = edges_c * normu;

    float a = alpha_p[0], be = beta_p[0], ga = gamma_p[0];
    float result = u_c + DTf * (curvature * a + transport * be + balloon * ga);

    out[((size_t)b * Hn + (y0 + ty)) * Wn + (x0 + tx)] = result;
}

extern "C" void kernel_launch(void* const* d_in, const int* in_sizes, int n_in,
                              void* d_out, int out_size) {
    const float* u     = (const float*)d_in[0];
    const float* img   = (const float*)d_in[1];
    const float* alpha = (const float*)d_in[2];
    const float* beta  = (const float*)d_in[3];
    const float* gamma = (const float*)d_in[4];
    float* out = (float*)d_out;

    init_max_kernel<<<1, 1>>>();

    dim3 rblk(256, 1, 1);
    dim3 rgrd((Wn + 255) / 256, Hn, Bn);
    reduce_max_kernel<<<rgrd, rblk>>>(img);

    dim3 blk(TX, TY, 1);
    dim3 grd(Wn / TX, Hn / TY, Bn);
    forcing_kernel<<<grd, blk>>>(u, img, alpha, beta, gamma, out);
}

// round 2
// speedup vs baseline: 1.3440x; 1.3440x over previous
#include <cuda_runtime.h>

#define Bn 32
#define Hn 512
#define Wn 512
#define EPSf 1e-7f
#define DTf 0.05f

__device__ unsigned int g_max_bits;

__global__ void init_max_kernel() { g_max_bits = 0u; }

__device__ __forceinline__ float frcp(float x) {
    float r; asm("rcp.approx.ftz.f32 %0, %1;" : "=f"(r) : "f"(x)); return r;
}
__device__ __forceinline__ float frsq(float x) {
    float r; asm("rsqrt.approx.ftz.f32 %0, %1;" : "=f"(r) : "f"(x)); return r;
}

// ---------------- Pass 1: max over e = ((sobel_x)^2+(sobel_y)^2)^2 ----------
// Register-rolling column kernel: 16 rows per thread, 3 guarded loads per row.
#define RROWS 16

__global__ __launch_bounds__(256) void reduce_max_kernel(const float* __restrict__ img) {
    const int x  = blockIdx.x * 256 + threadIdx.x;
    const int yb = blockIdx.y * RROWS;
    const int b  = blockIdx.z;
    const float* p = img + (size_t)b * Hn * Wn;

    const bool xm_ok = (x > 0);
    const bool xp_ok = (x < Wn - 1);

    float am0, am1, am2, ac0, ac1, ac2, ap0, ap1, ap2;

    // load row yb-1 -> am, row yb -> ac
    {
        int y = yb - 1;
        bool ok = (y >= 0);
        const float* r = p + (size_t)y * Wn;
        am0 = (ok && xm_ok) ? r[x - 1] : 0.0f;
        am1 = ok ? r[x] : 0.0f;
        am2 = (ok && xp_ok) ? r[x + 1] : 0.0f;
    }
    {
        const float* r = p + (size_t)yb * Wn;
        ac0 = xm_ok ? r[x - 1] : 0.0f;
        ac1 = r[x];
        ac2 = xp_ok ? r[x + 1] : 0.0f;
    }

    float m = 0.0f;
    #pragma unroll
    for (int k = 0; k < RROWS; k++) {
        int y = yb + k;
        int yn = y + 1;
        bool ok = (yn < Hn);
        const float* r = p + (size_t)yn * Wn;
        ap0 = (ok && xm_ok) ? r[x - 1] : 0.0f;
        ap1 = ok ? r[x] : 0.0f;
        ap2 = (ok && xp_ok) ? r[x + 1] : 0.0f;

        float sx = (am0 - am2) + 2.0f * (ac0 - ac2) + (ap0 - ap2);
        float sy = (am0 - ap0) + 2.0f * (am1 - ap1) + (am2 - ap2);
        float s = sx * sx + sy * sy;
        m = fmaxf(m, s * s);

        am0 = ac0; am1 = ac1; am2 = ac2;
        ac0 = ap0; ac1 = ap1; ac2 = ap2;
    }

    // warp max
    #pragma unroll
    for (int o = 16; o > 0; o >>= 1)
        m = fmaxf(m, __shfl_xor_sync(0xffffffffu, m, o));
    __shared__ float wmax[8];
    int lane = threadIdx.x & 31;
    int w = threadIdx.x >> 5;
    if (lane == 0) wmax[w] = m;
    __syncthreads();
    if (threadIdx.x < 8) {
        float v = wmax[threadIdx.x];
        #pragma unroll
        for (int o = 4; o > 0; o >>= 1)
            v = fmaxf(v, __shfl_xor_sync(0xffu, v, o));
        if (threadIdx.x == 0)
            atomicMax(&g_max_bits, __float_as_uint(v));  // all values >= 0
    }
}

// ---------------- Pass 2: fused forcing function ----------------------------
// Tile 64x16 outputs, block (16,16)=256 threads, 4 horizontal pixels/thread.
#define TDX 16
#define TDY 16
#define TX 64
#define TY 16
#define RXw 68
#define RYh 20
#define RXs 69
#define EXw 66
#define EYh 18
#define EXs 67

__global__ __launch_bounds__(TDX * TDY) void forcing_kernel(
    const float* __restrict__ u,
    const float* __restrict__ img,
    const float* __restrict__ alpha_p,
    const float* __restrict__ beta_p,
    const float* __restrict__ gamma_p,
    float* __restrict__ out)
{
    __shared__ float s_img[RYh][RXs];
    __shared__ float s_u[RYh][RXs];
    __shared__ float s_edges[EYh][EXs];
    __shared__ float s_px[EYh][EXs];
    __shared__ float s_py[EYh][EXs];

    const int tx = threadIdx.x;
    const int ty = threadIdx.y;
    const int tid = ty * TDX + tx;
    const int x0 = blockIdx.x * TX;
    const int y0 = blockIdx.y * TY;
    const int b  = blockIdx.z;

    const float* imgB = img + (size_t)b * Hn * Wn;
    const float* uB   = u   + (size_t)b * Hn * Wn;

    // --- load raw halo tiles (zero-padded SAME) ---
    #pragma unroll
    for (int i = tid; i < RYh * RXw; i += TDX * TDY) {
        int ry = i / RXw, rx = i - ry * RXw;
        int gy = y0 - 2 + ry;
        int gx = x0 - 2 + rx;
        float iv = 0.0f, uv = 0.0f;
        if ((unsigned)gy < (unsigned)Hn && (unsigned)gx < (unsigned)Wn) {
            size_t off = (size_t)gy * Wn + gx;
            iv = imgB[off];
            uv = uB[off];
        }
        s_img[ry][rx] = iv;
        s_u[ry][rx] = uv;
    }
    __syncthreads();

    const float maxv = __uint_as_float(g_max_bits);

    // --- extended intermediates: edges, px, py over 18 rows x 66 cols ------
    // strips of 4 columns: 17 strips x 18 rows = 306 tasks
    for (int t = tid; t < 17 * 18; t += TDX * TDY) {
        int eyi = t / 17;
        int st  = t - eyi * 17;
        int exi0 = st * 4;

        // raw rows eyi .. eyi+2, raw cols exi0 .. exi0+5 for img
        float i0[6], i1[6], i2[6], uc[6];
        #pragma unroll
        for (int k = 0; k < 6; k++) {
            i0[k] = s_img[eyi][exi0 + k];
            i1[k] = s_img[eyi + 1][exi0 + k];
            i2[k] = s_img[eyi + 2][exi0 + k];
            uc[k] = s_u[eyi + 1][exi0 + k];
        }
        float um[4], up[4];
        #pragma unroll
        for (int k = 0; k < 4; k++) {
            um[k] = s_u[eyi][exi0 + 1 + k];
            up[k] = s_u[eyi + 2][exi0 + 1 + k];
        }

        int gy = y0 - 1 + eyi;
        #pragma unroll
        for (int j = 0; j < 4; j++) {
            int exi = exi0 + j;
            if (exi >= EXw) break;
            int gx = x0 - 1 + exi;
            float edges = 0.0f, px = 0.0f, py = 0.0f;
            if ((unsigned)gy < (unsigned)Hn && (unsigned)gx < (unsigned)Wn) {
                float sx = (i0[j] - i0[j + 2]) + 2.0f * (i1[j] - i1[j + 2]) + (i2[j] - i2[j + 2]);
                float sy = (i0[j] - i2[j]) + 2.0f * (i0[j + 1] - i2[j + 1]) + (i0[j + 2] - i2[j + 2]);
                float s = sx * sx + sy * sy;
                float e = s * s;
                edges = maxv * frcp(e + maxv);      // == 1/(e/maxv + 1)
                float gux = uc[j + 2] - uc[j];
                float guy = um[j] - up[j];
                float q = gux * gux + guy * guy + EPSf;
                float rs = frsq(q);
                float normu = q * rs;               // sqrt(q)
                float inv = frcp(normu + EPSf);
                px = gux * inv;
                py = guy * inv;
            }
            s_edges[eyi][exi] = edges;
            s_px[eyi][exi] = px;
            s_py[eyi][exi] = py;
        }
    }
    __syncthreads();

    // --- final: 4 horizontal outputs per thread ---
    const int ey = ty + 1;         // ext row of center
    const int ex0 = tx * 4 + 1;    // ext col of first center
    const int ry = ty + 2;         // raw row of center
    const int rx0 = tx * 4 + 2;    // raw col of first center

    float uc2[6], ec[6], pxr[6];
    #pragma unroll
    for (int k = 0; k < 6; k++) {
        uc2[k] = s_u[ry][rx0 - 1 + k];
        ec[k]  = s_edges[ey][ex0 - 1 + k];
        pxr[k] = s_px[ey][ex0 - 1 + k];
    }
    float umm[4], upp[4], em[4], ep[4], pym[4], pyp[4];
    #pragma unroll
    for (int k = 0; k < 4; k++) {
        umm[k] = s_u[ry - 1][rx0 + k];
        upp[k] = s_u[ry + 1][rx0 + k];
        em[k]  = s_edges[ey - 1][ex0 + k];
        ep[k]  = s_edges[ey + 1][ex0 + k];
        pym[k] = s_py[ey - 1][ex0 + k];
        pyp[k] = s_py[ey + 1][ex0 + k];
    }

    const float a  = alpha_p[0];
    const float be = beta_p[0];
    const float ga = gamma_p[0];

    float res[4];
    #pragma unroll
    for (int j = 0; j < 4; j++) {
        float u_c = uc2[j + 1];
        float uxm = uc2[j];
        float uxp = uc2[j + 2];
        float uyp = umm[j];   // row y-1
        float uym = upp[j];   // row y+1

        float xp = uxp - u_c;
        float xn = u_c - uxm;
        float yp = uyp - u_c;
        float yn = u_c - uym;

        float gux = uxp - uxm;
        float guy = uyp - uym;
        float q = gux * gux + guy * guy + EPSf;
        float rs = frsq(q);
        float normu = q * rs;

        float gex = ec[j + 2] - ec[j];
        float gey = em[j] - ep[j];
        float edges_c = ec[j + 1];

        float kappa = (pxr[j + 2] - pxr[j]) + (pym[j] - pyp[j]);

        float fxp = fmaxf(gex, 0.0f);
        float fxn = fminf(gex, 0.0f);
        float fyp = fmaxf(gey, 0.0f);
        float fyn = fminf(gey, 0.0f);
        float transport = 20.0f * ((fxp * xp + fxn * xn) + (fyp * yp + fyn * yn));

        float curvature = edges_c * kappa * normu;
        float balloon   = edges_c * normu;

        res[j] = u_c + DTf * (curvature * a + transport * be + balloon * ga);
    }

    float4 v = make_float4(res[0], res[1], res[2], res[3]);
    size_t off = ((size_t)b * Hn + (y0 + ty)) * Wn + (x0 + tx * 4);
    *reinterpret_cast<float4*>(out + off) = v;
}

extern "C" void kernel_launch(void* const* d_in, const int* in_sizes, int n_in,
                              void* d_out, int out_size) {
    const float* u     = (const float*)d_in[0];
    const float* img   = (const float*)d_in[1];
    const float* alpha = (const float*)d_in[2];
    const float* beta  = (const float*)d_in[3];
    const float* gamma = (const float*)d_in[4];
    float* out = (float*)d_out;

    init_max_kernel<<<1, 1>>>();

    dim3 rblk(256, 1, 1);
    dim3 rgrd(Wn / 256, Hn / RROWS, Bn);
    reduce_max_kernel<<<rgrd, rblk>>>(img);

    dim3 blk(TDX, TDY, 1);
    dim3 grd(Wn / TX, Hn / TY, Bn);
    forcing_kernel<<<grd, blk>>>(u, img, alpha, beta, gamma, out);
}

// round 3
// speedup vs baseline: 1.6186x; 1.2043x over previous
#include <cuda_runtime.h>

#define Bn 32
#define Hn 512
#define Wn 512
#define EPSf 1e-7f
#define DTf 0.05f

__device__ float g_maxv;
__device__ float g_partial[512];

__device__ __forceinline__ float frcp(float x) {
    float r; asm("rcp.approx.ftz.f32 %0, %1;" : "=f"(r) : "f"(x)); return r;
}
__device__ __forceinline__ float frsq(float x) {
    float r; asm("rsqrt.approx.ftz.f32 %0, %1;" : "=f"(r) : "f"(x)); return r;
}
__device__ __forceinline__ void ld8(float* d, const float* s) {
    float4 a = *(const float4*)s;
    float4 b = *(const float4*)(s + 4);
    d[0]=a.x; d[1]=a.y; d[2]=a.z; d[3]=a.w;
    d[4]=b.x; d[5]=b.y; d[6]=b.z; d[7]=b.w;
}

// ---------------- Pass 1: partial max of e = ((sobel_x)^2+(sobel_y)^2)^2 ----
// block (32,8); each lane owns 4 cols, rolls 16 rows. grid (4,4,32) -> 512 partials.
__global__ __launch_bounds__(256) void reduce_max_kernel(const float* __restrict__ img) {
    const int lane = threadIdx.x;
    const int gx0 = blockIdx.x * 128 + lane * 4;
    const int ybase = blockIdx.y * 128 + threadIdx.y * 16;
    const int b = blockIdx.z;
    const float* p = img + (size_t)b * Hn * Wn;

    float wm[6], wc[6], wp[6];

    auto load_row = [&](int y, float* w) {
        float4 v = make_float4(0.f, 0.f, 0.f, 0.f);
        bool ok = ((unsigned)y < (unsigned)Hn);        // warp-uniform (y uniform per warp)
        if (ok) v = *(const float4*)(p + (size_t)y * Wn + gx0);
        float l = __shfl_up_sync(0xffffffffu, v.w, 1);
        float r = __shfl_down_sync(0xffffffffu, v.x, 1);
        if (lane == 0)  l = (ok && gx0 > 0)      ? p[(size_t)y * Wn + gx0 - 1] : 0.f;
        if (lane == 31) r = (ok && gx0 + 4 < Wn) ? p[(size_t)y * Wn + gx0 + 4] : 0.f;
        w[0]=l; w[1]=v.x; w[2]=v.y; w[3]=v.z; w[4]=v.w; w[5]=r;
    };

    load_row(ybase - 1, wm);
    load_row(ybase,     wc);
    float m = 0.f;
    #pragma unroll
    for (int k = 0; k < 16; k++) {
        load_row(ybase + k + 1, wp);
        #pragma unroll
        for (int j = 0; j < 4; j++) {
            float sx = (wm[j] - wm[j+2]) + 2.f*(wc[j] - wc[j+2]) + (wp[j] - wp[j+2]);
            float sy = (wm[j] - wp[j]) + 2.f*(wm[j+1] - wp[j+1]) + (wm[j+2] - wp[j+2]);
            float s = sx*sx + sy*sy;
            m = fmaxf(m, s*s);
        }
        #pragma unroll
        for (int q = 0; q < 6; q++) { wm[q] = wc[q]; wc[q] = wp[q]; }
    }

    #pragma unroll
    for (int o = 16; o > 0; o >>= 1)
        m = fmaxf(m, __shfl_xor_sync(0xffffffffu, m, o));
    __shared__ float wmax[8];
    if (lane == 0) wmax[threadIdx.y] = m;
    __syncthreads();
    if (threadIdx.y == 0 && lane < 8) {
        float v = wmax[lane];
        #pragma unroll
        for (int o = 4; o > 0; o >>= 1)
            v = fmaxf(v, __shfl_xor_sync(0xffu, v, o));
        if (lane == 0) {
            int bid = (blockIdx.z * gridDim.y + blockIdx.y) * gridDim.x + blockIdx.x;
            g_partial[bid] = v;
        }
    }
}

// ---------------- Pass 1b: final max over 512 partials (replaces init) ------
__global__ __launch_bounds__(512) void reduce_final_kernel() {
    int tid = threadIdx.x;
    float v = g_partial[tid];
    #pragma unroll
    for (int o = 16; o > 0; o >>= 1)
        v = fmaxf(v, __shfl_xor_sync(0xffffffffu, v, o));
    __shared__ float sm[16];
    int lane = tid & 31, w = tid >> 5;
    if (lane == 0) sm[w] = v;
    __syncthreads();
    if (tid < 16) {
        float x = sm[tid];
        #pragma unroll
        for (int o = 8; o > 0; o >>= 1)
            x = fmaxf(x, __shfl_xor_sync(0xffffu, x, o));
        if (tid == 0) g_maxv = x;
    }
}

// ---------------- Pass 2: fused forcing function ----------------------------
// Tile 64x16 outputs. Raw tile: rows y0-2..y0+17 (20), cols x0-4..x0+67 (72, 16B-aligned).
// Ext tile: rows y0-1..y0+16 (18), ext col e <-> global x0-1+e <-> raw col e+3.
#define RS 72
#define ES 68

__global__ __launch_bounds__(256, 4) void forcing_kernel(
    const float* __restrict__ u,
    const float* __restrict__ img,
    const float* __restrict__ alpha_p,
    const float* __restrict__ beta_p,
    const float* __restrict__ gamma_p,
    float* __restrict__ out)
{
    __shared__ __align__(16) float s_img[20][RS];
    __shared__ __align__(16) float s_u[20][RS];
    __shared__ __align__(16) float s_edges[18][ES];
    __shared__ __align__(16) float s_px[18][ES];
    __shared__ __align__(16) float s_py[18][ES];

    const int tx = threadIdx.x;           // 0..15
    const int ty = threadIdx.y;           // 0..15
    const int tid = ty * 16 + tx;
    const int x0 = blockIdx.x * 64;
    const int y0 = blockIdx.y * 16;
    const int b  = blockIdx.z;

    const float* imgB = img + (size_t)b * Hn * Wn;
    const float* uB   = u   + (size_t)b * Hn * Wn;

    const bool interior = (x0 >= 4) && (x0 + 68 <= Wn) && (y0 >= 2) && (y0 + 18 <= Hn);

    // --- phase 1: load raw halo tiles ---
    if (interior) {
        const float* ib = imgB + (size_t)(y0 - 2) * Wn + (x0 - 4);
        const float* ub = uB   + (size_t)(y0 - 2) * Wn + (x0 - 4);
        #pragma unroll
        for (int t = tid; t < 360; t += 256) {
            int row = t / 18;
            int c = (t - row * 18) * 4;
            size_t g = (size_t)row * Wn + c;
            *(float4*)&s_img[row][c] = *(const float4*)(ib + g);
            *(float4*)&s_u[row][c]   = *(const float4*)(ub + g);
        }
    } else {
        for (int t = tid; t < 1440; t += 256) {
            int row = t / RS;
            int rx = t - row * RS;
            int gy = y0 - 2 + row;
            int gx = x0 - 4 + rx;
            float iv = 0.f, uv = 0.f;
            if ((unsigned)gy < (unsigned)Hn && (unsigned)gx < (unsigned)Wn) {
                size_t off = (size_t)gy * Wn + gx;
                iv = imgB[off];
                uv = uB[off];
            }
            s_img[row][rx] = iv;
            s_u[row][rx] = uv;
        }
    }
    __syncthreads();

    const float maxv = g_maxv;

    // --- phase 2: ext intermediates (18 rows x 17 strips of 4 cols) ---
    for (int t = tid; t < 306; t += 256) {
        int eyi = t / 17;
        int st  = (t - eyi * 17) * 4;    // ext col base; f8 loads from raw col st
        float f0[8], f1[8], f2[8], uc[8], um[8], up[8];
        ld8(f0, &s_img[eyi][st]);
        ld8(f1, &s_img[eyi + 1][st]);
        ld8(f2, &s_img[eyi + 2][st]);
        ld8(uc, &s_u[eyi + 1][st]);
        ld8(um, &s_u[eyi][st]);
        ld8(up, &s_u[eyi + 2][st]);
        int gy = y0 - 1 + eyi;
        float e4[4], px4[4], py4[4];
        #pragma unroll
        for (int j = 0; j < 4; j++) {
            // ext col = st + j; raw center idx = j+3
            float sx = (f0[j+2] - f0[j+4]) + 2.f*(f1[j+2] - f1[j+4]) + (f2[j+2] - f2[j+4]);
            float sy = (f0[j+2] - f2[j+2]) + 2.f*(f0[j+3] - f2[j+3]) + (f0[j+4] - f2[j+4]);
            float s = sx*sx + sy*sy;
            float e = s*s;
            float edges = maxv * frcp(e + maxv);     // == 1/(e/maxv + 1)
            float gux = uc[j+4] - uc[j+2];
            float guy = um[j+3] - up[j+3];
            float q = gux*gux + guy*guy + EPSf;
            float rs = frsq(q);
            float normu = q * rs;                     // sqrt(q)
            float inv = frcp(normu + EPSf);
            bool ok = interior ||
                      ((unsigned)gy < (unsigned)Hn &&
                       (unsigned)(x0 - 1 + st + j) < (unsigned)Wn);
            e4[j]  = ok ? edges : 0.f;
            px4[j] = ok ? gux * inv : 0.f;
            py4[j] = ok ? guy * inv : 0.f;
        }
        *(float4*)&s_edges[eyi][st] = make_float4(e4[0], e4[1], e4[2], e4[3]);
        *(float4*)&s_px[eyi][st]    = make_float4(px4[0], px4[1], px4[2], px4[3]);
        *(float4*)&s_py[eyi][st]    = make_float4(py4[0], py4[1], py4[2], py4[3]);
    }
    __syncthreads();

    // --- phase 3: 4 outputs per thread ---
    const int ey = ty + 1;
    const int e0 = tx * 4;        // centers at ext cols e0+1..e0+4
    const int ry = ty + 2;
    const int r0 = tx * 4;        // centers at raw cols r0+4..r0+7

    float ec[8], pxr[8], em[8], ep[8], pym[8], pyp[8], ur[12];
    ld8(ec,  &s_edges[ey][e0]);
    ld8(pxr, &s_px[ey][e0]);
    ld8(em,  &s_edges[ey - 1][e0]);
    ld8(ep,  &s_edges[ey + 1][e0]);
    ld8(pym, &s_py[ey - 1][e0]);
    ld8(pyp, &s_py[ey + 1][e0]);
    ld8(ur,  &s_u[ry][r0]);
    *(float4*)&ur[8] = *(const float4*)&s_u[ry][r0 + 8];
    float umm[4], upp[4];
    *(float4*)&umm[0] = *(const float4*)&s_u[ry - 1][r0 + 4];
    *(float4*)&upp[0] = *(const float4*)&s_u[ry + 1][r0 + 4];

    const float a  = alpha_p[0];
    const float be = beta_p[0];
    const float ga = gamma_p[0];

    float res[4];
    #pragma unroll
    for (int j = 0; j < 4; j++) {
        float u_c = ur[4 + j];
        float uxm = ur[3 + j];
        float uxp = ur[5 + j];
        float uyp = umm[j];    // row y-1
        float uym = upp[j];    // row y+1

        float xp = uxp - u_c;
        float xn = u_c - uxm;
        float yp = uyp - u_c;
        float yn = u_c - uym;

        float gux = uxp - uxm;
        float guy = uyp - uym;
        float q = gux*gux + guy*guy + EPSf;
        float rs = frsq(q);
        float normu = q * rs;

        float gex = ec[j + 2] - ec[j];
        float gey = em[j + 1] - ep[j + 1];
        float edges_c = ec[j + 1];

        float kappa = (pxr[j + 2] - pxr[j]) + (pym[j + 1] - pyp[j + 1]);

        float fxp = fmaxf(gex, 0.f);
        float fxn = fminf(gex, 0.f);
        float fyp = fmaxf(gey, 0.f);
        float fyn = fminf(gey, 0.f);
        float transport = 20.f * ((fxp * xp + fxn * xn) + (fyp * yp + fyn * yn));

        float curvature = edges_c * kappa * normu;
        float balloon   = edges_c * normu;

        res[j] = u_c + DTf * (curvature * a + transport * be + balloon * ga);
    }

    size_t off = ((size_t)b * Hn + (y0 + ty)) * Wn + (x0 + tx * 4);
    *(float4*)(out + off) = make_float4(res[0], res[1], res[2], res[3]);
}

extern "C" void kernel_launch(void* const* d_in, const int* in_sizes, int n_in,
                              void* d_out, int out_size) {
    const float* u     = (const float*)d_in[0];
    const float* img   = (const float*)d_in[1];
    const float* alpha = (const float*)d_in[2];
    const float* beta  = (const float*)d_in[3];
    const float* gamma = (const float*)d_in[4];
    float* out = (float*)d_out;

    dim3 rblk(32, 8, 1);
    dim3 rgrd(4, 4, Bn);
    reduce_max_kernel<<<rgrd, rblk>>>(img);

    reduce_final_kernel<<<1, 512>>>();

    dim3 blk(16, 16, 1);
    dim3 grd(Wn / 64, Hn / 16, Bn);
    forcing_kernel<<<grd, blk>>>(u, img, alpha, beta, gamma, out);
}

// round 4
// speedup vs baseline: 2.1245x; 1.3125x over previous
#include <cuda_runtime.h>

#define Hn 512
#define Wn 512
#define Bn 32
#define EPSf 1e-7f
#define DTf 0.05f

__device__ float g_partial[1024];

__device__ __forceinline__ float frcp(float x) {
    float r; asm("rcp.approx.ftz.f32 %0, %1;" : "=f"(r) : "f"(x)); return r;
}
__device__ __forceinline__ float frsq(float x) {
    float r; asm("rsqrt.approx.ftz.f32 %0, %1;" : "=f"(r) : "f"(x)); return r;
}

// ---------------- Pass 1: partial max of e = ((sobel_x)^2+(sobel_y)^2)^2 ----
// block (32,8); lane owns 4 cols; thread rolls 8 rows. grid (4,8,32) -> 1024 partials.
__global__ __launch_bounds__(256) void reduce_max_kernel(const float* __restrict__ img) {
    const int lane = threadIdx.x;
    const int x0 = blockIdx.x * 128 + lane * 4;
    const int yb = (blockIdx.y * 8 + threadIdx.y) * 8;
    const float* p = img + (size_t)blockIdx.z * Hn * Wn;

    float w0[6], w1[6], w2[6];
    auto ldr = [&](int y, float* w) {
        bool ok = ((unsigned)y < (unsigned)Hn);
        const float* r = p + (size_t)y * Wn + x0;
        float4 f = make_float4(0.f, 0.f, 0.f, 0.f);
        if (ok) f = *(const float4*)r;
        w[1] = f.x; w[2] = f.y; w[3] = f.z; w[4] = f.w;
        w[0] = (ok && x0 >= 1) ? r[-1] : 0.f;
        w[5] = (ok && x0 + 4 < Wn) ? r[4] : 0.f;
    };

    ldr(yb - 1, w0);
    ldr(yb, w1);
    float m = 0.f;
    #pragma unroll
    for (int k = 0; k < 8; ++k) {
        ldr(yb + k + 1, w2);
        #pragma unroll
        for (int j = 0; j < 4; ++j) {
            float sx = (w0[j] - w0[j+2]) + 2.f * (w1[j] - w1[j+2]) + (w2[j] - w2[j+2]);
            float sy = (w0[j] - w2[j]) + 2.f * (w0[j+1] - w2[j+1]) + (w0[j+2] - w2[j+2]);
            float s = sx * sx + sy * sy;
            m = fmaxf(m, s * s);
        }
        #pragma unroll
        for (int q = 0; q < 6; ++q) { w0[q] = w1[q]; w1[q] = w2[q]; }
    }

    #pragma unroll
    for (int o = 16; o > 0; o >>= 1)
        m = fmaxf(m, __shfl_xor_sync(0xffffffffu, m, o));
    __shared__ float wmax[8];
    if (lane == 0) wmax[threadIdx.y] = m;
    __syncthreads();
    if (threadIdx.y == 0 && lane == 0) {
        float v = wmax[0];
        #pragma unroll
        for (int i = 1; i < 8; ++i) v = fmaxf(v, wmax[i]);
        int bid = ((int)blockIdx.z * 8 + blockIdx.y) * 4 + blockIdx.x;
        g_partial[bid] = v;
    }
}

// ---------------- Pass 2: register-rolling fused forcing ---------------------
struct W8 { float v[8]; };
struct I6 { float e[6]; float p[6]; float q[4]; };

__device__ __forceinline__ W8 load_row8(const float* __restrict__ base, int y, int c0, int lane) {
    W8 w;
    float4 f = make_float4(0.f, 0.f, 0.f, 0.f);
    bool rok = ((unsigned)y < (unsigned)Hn);
    const float* r = base + (size_t)y * Wn + c0;
    if (rok) f = *(const float4*)r;
    float l1 = __shfl_up_sync(0xffffffffu, f.w, 1);
    float l2 = __shfl_up_sync(0xffffffffu, f.z, 1);
    float r1 = __shfl_down_sync(0xffffffffu, f.x, 1);
    float r2 = __shfl_down_sync(0xffffffffu, f.y, 1);
    if (lane == 0) {
        l1 = (rok && c0 >= 1) ? r[-1] : 0.f;
        l2 = (rok && c0 >= 2) ? r[-2] : 0.f;
    }
    if (lane == 31) {
        r1 = (rok && c0 + 4 < Wn) ? r[4] : 0.f;
        r2 = (rok && c0 + 5 < Wn) ? r[5] : 0.f;
    }
    w.v[0] = l2; w.v[1] = l1; w.v[2] = f.x; w.v[3] = f.y;
    w.v[4] = f.z; w.v[5] = f.w; w.v[6] = r1; w.v[7] = r2;
    return w;
}

// intermediates (edges, px, py) at row y, cols c0-1 .. c0+4 (6-wide; py center 4)
__device__ __forceinline__ I6 intermed(const W8& im, const W8& ic, const W8& ip,
                                       const W8& um, const W8& uc, const W8& up,
                                       int y, int c0, float maxv) {
    I6 o;
    bool rok = ((unsigned)y < (unsigned)Hn);
    #pragma unroll
    for (int j = 0; j < 6; ++j) {
        float sx = (im.v[j] - im.v[j+2]) + 2.f * (ic.v[j] - ic.v[j+2]) + (ip.v[j] - ip.v[j+2]);
        float sy = (im.v[j] - ip.v[j]) + 2.f * (im.v[j+1] - ip.v[j+1]) + (im.v[j+2] - ip.v[j+2]);
        float s = sx * sx + sy * sy;
        float e = s * s;
        float edges = maxv * frcp(e + maxv);          // == 1/(e/maxv + 1)
        float gux = uc.v[j+2] - uc.v[j];
        float guy = um.v[j+1] - up.v[j+1];
        float qq = gux * gux + guy * guy + EPSf;
        float rs = frsq(qq);
        float normu = qq * rs;                         // sqrt(qq)
        float inv = frcp(normu + EPSf);
        int cc = c0 - 1 + j;
        bool ok = rok && ((unsigned)cc < (unsigned)Wn);
        o.e[j] = ok ? edges : 0.f;
        o.p[j] = ok ? gux * inv : 0.f;
        if (j >= 1 && j <= 4) o.q[j - 1] = ok ? guy * inv : 0.f;
    }
    return o;
}

// One pipeline step at intermediate-row rr:
//  - compute I row rr from (mI,cI,pI)=img rows rr-1..rr+1, (mU,cU,pU)=u rows rr-1..rr+1
//  - emit output row ey=rr-1 from (Ea,Eb,Ecv)=rows rr-2..rr, u rows: st=rr-2 ctr, mU, cU
//  - stash mU center, load rows rr+2 into the m-slots
#define STEP(mI, cI, pI, mU, cU, pU, Ea, Eb, Ecv, rr)                          \
    do {                                                                        \
        Ecv = intermed(mI, cI, pI, mU, cU, pU, (rr), c0, maxv);                 \
        int ey = (rr) - 1;                                                      \
        if (ey < ys + 32) {                                                     \
            float rr4[4];                                                       \
            _Pragma("unroll")                                                   \
            for (int i = 0; i < 4; ++i) {                                       \
                float u_c = mU.v[i+2];                                          \
                float uxm = mU.v[i+1];                                          \
                float uxp = mU.v[i+3];                                          \
                float uyp = st[i];          /* row ey-1 */                      \
                float uym = cU.v[i+2];      /* row ey+1 */                      \
                float xp = uxp - u_c;                                           \
                float xn = u_c - uxm;                                           \
                float yp = uyp - u_c;                                           \
                float yn = u_c - uym;                                           \
                float gux = uxp - uxm;                                          \
                float guy = uyp - uym;                                          \
                float qq = gux * gux + guy * guy + EPSf;                        \
                float rs = frsq(qq);                                            \
                float normu = qq * rs;                                          \
                float gex = Eb.e[i+2] - Eb.e[i];                                \
                float gey = Ea.e[i+1] - Ecv.e[i+1];                             \
                float edges_c = Eb.e[i+1];                                      \
                float kappa = (Eb.p[i+2] - Eb.p[i]) + (Ea.q[i] - Ecv.q[i]);     \
                float fxp = fmaxf(gex, 0.f);                                    \
                float fxn = fminf(gex, 0.f);                                    \
                float fyp = fmaxf(gey, 0.f);                                    \
                float fyn = fminf(gey, 0.f);                                    \
                float transport = 20.f * ((fxp*xp + fxn*xn) + (fyp*yp + fyn*yn));\
                float curvature = edges_c * kappa * normu;                      \
                float balloon   = edges_c * normu;                              \
                rr4[i] = u_c + DTf * (curvature*a + transport*be + balloon*ga); \
            }                                                                   \
            *(float4*)(oB + (size_t)ey * Wn + c0) =                             \
                make_float4(rr4[0], rr4[1], rr4[2], rr4[3]);                    \
        }                                                                       \
        st[0] = mU.v[2]; st[1] = mU.v[3]; st[2] = mU.v[4]; st[3] = mU.v[5];     \
        mI = load_row8(pi, (rr) + 2, c0, lane);                                 \
        mU = load_row8(pu, (rr) + 2, c0, lane);                                 \
    } while (0)

__global__ __launch_bounds__(256, 2) void forcing_kernel(
    const float* __restrict__ u,
    const float* __restrict__ img,
    const float* __restrict__ alpha_p,
    const float* __restrict__ beta_p,
    const float* __restrict__ gamma_p,
    float* __restrict__ out)
{
    // prologue: reduce 1024 partial maxima (replaces a separate kernel)
    __shared__ float s_red[8];
    __shared__ float s_maxv;
    const int tid = threadIdx.x;
    {
        float v = fmaxf(fmaxf(g_partial[tid], g_partial[tid + 256]),
                        fmaxf(g_partial[tid + 512], g_partial[tid + 768]));
        #pragma unroll
        for (int o = 16; o > 0; o >>= 1)
            v = fmaxf(v, __shfl_xor_sync(0xffffffffu, v, o));
        if ((tid & 31) == 0) s_red[tid >> 5] = v;
        __syncthreads();
        if (tid == 0) {
            float m = s_red[0];
            #pragma unroll
            for (int i = 1; i < 8; ++i) m = fmaxf(m, s_red[i]);
            s_maxv = m;
        }
        __syncthreads();
    }
    const float maxv = s_maxv;

    const int lane = tid & 31;
    const int wrp  = tid >> 5;
    const int ww   = blockIdx.x * 8 + wrp;   // 0..2047 warp tasks
    const int bb   = ww >> 6;                // batch
    const int rem  = ww & 63;
    const int ys   = (rem >> 2) * 32;        // segment start row
    const int c0   = (rem & 3) * 128 + lane * 4;

    const float* pu = u   + (size_t)bb * Hn * Wn;
    const float* pi = img + (size_t)bb * Hn * Wn;
    float* oB = out + (size_t)bb * Hn * Wn;

    const float a  = alpha_p[0];
    const float be = beta_p[0];
    const float ga = gamma_p[0];

    // ---- priming ----
    W8 t_m2 = load_row8(pi, ys - 2, c0, lane);
    W8 t_m1 = load_row8(pi, ys - 1, c0, lane);
    W8 t_0  = load_row8(pi, ys,     c0, lane);
    W8 s_m2 = load_row8(pu, ys - 2, c0, lane);
    W8 s_m1 = load_row8(pu, ys - 1, c0, lane);
    W8 s_0  = load_row8(pu, ys,     c0, lane);
    I6 Ia = intermed(t_m2, t_m1, t_0, s_m2, s_m1, s_0, ys - 1, c0, maxv);
    W8 t_1 = load_row8(pi, ys + 1, c0, lane);
    W8 s_1 = load_row8(pu, ys + 1, c0, lane);
    I6 Ib = intermed(t_m1, t_0, t_1, s_m1, s_0, s_1, ys, c0, maxv);
    W8 t_2 = load_row8(pi, ys + 2, c0, lane);
    W8 s_2 = load_row8(pu, ys + 2, c0, lane);

    float st[4] = { s_m1.v[2], s_m1.v[3], s_m1.v[4], s_m1.v[5] };

    W8 imA = t_0, imB = t_1, imC = t_2;
    W8 uwA = s_0, uwB = s_1, uwC = s_2;
    I6 Ic;

    int r = ys + 1;
    #pragma unroll 1
    for (int it = 0; it < 11; ++it) {
        STEP(imA, imB, imC, uwA, uwB, uwC, Ia, Ib, Ic, r);
        STEP(imB, imC, imA, uwB, uwC, uwA, Ib, Ic, Ia, r + 1);
        STEP(imC, imA, imB, uwC, uwA, uwB, Ic, Ia, Ib, r + 2);
        r += 3;
    }
}

extern "C" void kernel_launch(void* const* d_in, const int* in_sizes, int n_in,
                              void* d_out, int out_size) {
    const float* u     = (const float*)d_in[0];
    const float* img   = (const float*)d_in[1];
    const float* alpha = (const float*)d_in[2];
    const float* beta  = (const float*)d_in[3];
    const float* gamma = (const float*)d_in[4];
    float* out = (float*)d_out;

    dim3 rblk(32, 8, 1);
    dim3 rgrd(4, 8, Bn);
    reduce_max_kernel<<<rgrd, rblk>>>(img);

    forcing_kernel<<<256, 256>>>(u, img, alpha, beta, gamma, out);
}